// round 1
// baseline (speedup 1.0000x reference)
#include <cuda_runtime.h>

// expm(A - A^T) for N=2048 fp32 via scaling-and-squaring + Taylor/Horner.
//   S = (A - A^T) / 2^SEXP
//   M = I + S/D                       (elementwise)
//   for k = D-1 .. 1:  M = I + (S/k) * M   (GEMM + identity epilogue)
//   repeat SEXP times: M = M * M           (GEMM)
// Truncation error ~ (||S||/2^SEXP)^(D+1)/(D+1)! ~ 4e-16 for ||S||~1.3.

#define MATN 2048
constexpr int SEXP = 4;   // number of squarings
constexpr int DEG  = 8;   // Taylor degree

// Scratch (device globals — no allocation allowed in kernel_launch)
__device__ float g_S[MATN * MATN];
__device__ float g_M[MATN * MATN];
__device__ float g_T[MATN * MATN];

// ---------------------------------------------------------------------------
// S = (A - A^T) * scale, tiled transpose for coalescing
// ---------------------------------------------------------------------------
__global__ void skew_kernel(const float* __restrict__ A, float* __restrict__ S,
                            float scale) {
    __shared__ float tileT[32][33];  // holds A^T block, padded
    int bx = blockIdx.x * 32;
    int by = blockIdx.y * 32;
    int tx = threadIdx.x;
    int ty = threadIdx.y;

    // Load the transposed-source block A[bx.., by..] coalesced
    #pragma unroll
    for (int r = 0; r < 32; r += 8) {
        tileT[ty + r][tx] = A[(bx + ty + r) * MATN + (by + tx)];
    }
    __syncthreads();

    // S[by+i][bx+j] = (A[by+i][bx+j] - A[bx+j][by+i]) * scale
    #pragma unroll
    for (int r = 0; r < 32; r += 8) {
        int row = by + ty + r;
        int col = bx + tx;
        float a  = A[row * MATN + col];
        float at = tileT[tx][ty + r];
        S[row * MATN + col] = (a - at) * scale;
    }
}

// ---------------------------------------------------------------------------
// M = S * alpha + I
// ---------------------------------------------------------------------------
__global__ void init_horner_kernel(const float* __restrict__ S,
                                   float* __restrict__ M, float alpha) {
    int idx = blockIdx.x * blockDim.x + threadIdx.x;
    int row = idx / MATN;
    int col = idx - row * MATN;
    float v = S[idx] * alpha;
    if (row == col) v += 1.0f;
    M[idx] = v;
}

// ---------------------------------------------------------------------------
// C = alpha * A*B (+ I if ADD_I).  128x128 tile, BK=8, 256 threads, 8x8/thread
// ---------------------------------------------------------------------------
template <bool ADD_I>
__global__ __launch_bounds__(256, 2)
void sgemm128(const float* __restrict__ A, const float* __restrict__ B,
              float* __restrict__ C, float alpha) {
    __shared__ float As[8][128];   // A tile, transposed (k-major)
    __shared__ float Bs[8][128];

    const int tid  = threadIdx.x;
    const int brow = blockIdx.y * 128;
    const int bcol = blockIdx.x * 128;

    // A-tile load mapping: 128x8 floats, float4 per thread
    const int arow  = tid >> 1;          // 0..127
    const int acol4 = (tid & 1) << 2;    // 0 or 4
    // B-tile load mapping: 8x128 floats, float4 per thread
    const int brow8 = tid >> 5;          // 0..7
    const int bcol4 = (tid & 31) << 2;   // 0..124

    const int ty = tid >> 4;             // 0..15 (row group)
    const int tx = tid & 15;             // 0..15 (col group)

    float acc[8][8];
    #pragma unroll
    for (int i = 0; i < 8; i++)
        #pragma unroll
        for (int j = 0; j < 8; j++) acc[i][j] = 0.0f;

    const float* Aptr = A + (brow + arow) * MATN + acol4;
    const float* Bptr = B + brow8 * MATN + bcol + bcol4;

    for (int k0 = 0; k0 < MATN; k0 += 8) {
        float4 a4 = *reinterpret_cast<const float4*>(Aptr + k0);
        float4 b4 = *reinterpret_cast<const float4*>(Bptr + (long)k0 * MATN);
        As[acol4 + 0][arow] = a4.x;
        As[acol4 + 1][arow] = a4.y;
        As[acol4 + 2][arow] = a4.z;
        As[acol4 + 3][arow] = a4.w;
        *reinterpret_cast<float4*>(&Bs[brow8][bcol4]) = b4;
        __syncthreads();

        #pragma unroll
        for (int k = 0; k < 8; k++) {
            float ra[8], rb[8];
            #pragma unroll
            for (int i = 0; i < 8; i++) ra[i] = As[k][ty * 8 + i];
            #pragma unroll
            for (int j = 0; j < 8; j++) rb[j] = Bs[k][tx * 8 + j];
            #pragma unroll
            for (int i = 0; i < 8; i++)
                #pragma unroll
                for (int j = 0; j < 8; j++)
                    acc[i][j] = fmaf(ra[i], rb[j], acc[i][j]);
        }
        __syncthreads();
    }

    // Epilogue
    #pragma unroll
    for (int i = 0; i < 8; i++) {
        int row  = brow + ty * 8 + i;
        int col0 = bcol + tx * 8;
        float out[8];
        #pragma unroll
        for (int j = 0; j < 8; j++) {
            float v = acc[i][j] * alpha;
            if (ADD_I && row == (col0 + j)) v += 1.0f;
            out[j] = v;
        }
        float4* cp = reinterpret_cast<float4*>(C + (long)row * MATN + col0);
        cp[0] = make_float4(out[0], out[1], out[2], out[3]);
        cp[1] = make_float4(out[4], out[5], out[6], out[7]);
    }
}

// ---------------------------------------------------------------------------
extern "C" void kernel_launch(void* const* d_in, const int* in_sizes, int n_in,
                              void* d_out, int out_size) {
    const float* A = (const float*)d_in[0];
    float* out = (float*)d_out;

    float *S, *M, *T;
    cudaGetSymbolAddress((void**)&S, g_S);
    cudaGetSymbolAddress((void**)&M, g_M);
    cudaGetSymbolAddress((void**)&T, g_T);

    const float inv_scale = 1.0f / (float)(1 << SEXP);

    // 1) S = (A - A^T) / 2^SEXP
    {
        dim3 blk(32, 8);
        dim3 grd(MATN / 32, MATN / 32);
        skew_kernel<<<grd, blk>>>(A, S, inv_scale);
    }

    // 2) M = I + S/DEG
    {
        int threads = 256;
        int blocks = (MATN * MATN) / threads;
        init_horner_kernel<<<blocks, threads>>>(S, M, 1.0f / (float)DEG);
    }

    dim3 gblk(256);
    dim3 ggrd(MATN / 128, MATN / 128);

    // 3) Horner: M = I + (S/k) * M, k = DEG-1 .. 1
    for (int k = DEG - 1; k >= 1; k--) {
        sgemm128<true><<<ggrd, gblk>>>(S, M, T, 1.0f / (float)k);
        float* tmp = M; M = T; T = tmp;
    }

    // 4) SEXP squarings; last one writes to d_out
    for (int s = 0; s < SEXP - 1; s++) {
        sgemm128<false><<<ggrd, gblk>>>(M, M, T, 1.0f);
        float* tmp = M; M = T; T = tmp;
    }
    sgemm128<false><<<ggrd, gblk>>>(M, M, out, 1.0f);
}